// round 6
// baseline (speedup 1.0000x reference)
#include <cuda_runtime.h>
#include <cuda_bf16.h>
#include <math.h>

typedef unsigned long long u64;
#define M_TOTAL 32768
#define D_MODEL 1024
#define HALF 32
#define T_SEQ 8192
#define TAPS 32

__device__ float g_xp[M_TOTAL * HALF];
__device__ float g_y[M_TOTAL * HALF];
__device__ u64   g_Kp[TAPS * 16];

__device__ __forceinline__ u64 fma2(u64 a, u64 b, u64 c) {
    u64 d; asm("fma.rn.f32x2 %0, %1, %2, %3;" : "=l"(d) : "l"(a), "l"(b), "l"(c)); return d;
}
__device__ __forceinline__ u64 pack2(float lo, float hi) {
    u64 r; asm("mov.b64 %0, {%1, %2};" : "=l"(r) : "f"(lo), "f"(hi)); return r;
}
__device__ __forceinline__ float2 unpack2(u64 v) {
    float2 f; asm("mov.b64 {%0, %1}, %2;" : "=f"(f.x), "=f"(f.y) : "l"(v)); return f;
}

// FIR taps: K[n,s] = exp(gain_n - tau*dt*s) * cos(s*angle_n), packed mode-pairs.
__global__ void k_prep(const float* __restrict__ log_tau, const float* __restrict__ freq,
                       const float* __restrict__ Bp, const float* __restrict__ Cp,
                       const float* __restrict__ log_dt) {
    int tid = threadIdx.x, s = tid >> 4, np = tid & 15;
    double dt = exp((double)log_dt[0]);
    float k[2];
#pragma unroll
    for (int j = 0; j < 2; j++) {
        int n = np * 2 + j;
        double tau   = fmax(exp((double)log_tau[n]), 1e-4);
        double angle = (double)freq[n] * dt;
        double gain  = log(fabs((double)Bp[n]) + 1e-9) + log(fabs((double)Cp[n]) + 1e-9);
        k[j] = (float)(exp(gain - tau * dt * (double)s) * cos((double)s * angle));
    }
    g_Kp[s * 16 + np] = pack2(k[0], k[1]);
}

// GEMM1: xp[m,n] = sum_d x[m,d]*Win[n,d]. 256 rows/block, k-chunks of 32.
__global__ __launch_bounds__(256, 1)
void k_proj(const float* __restrict__ x, const float* __restrict__ Win) {
    __shared__ float xs[32 * 260];   // [k][row]
    __shared__ float ws[32 * 36];    // [k][mode]
    const int tid = threadIdx.x, m0 = blockIdx.x * 256;
    const int rg = tid >> 2, mg = tid & 3;        // compute: rows rg*4, modes mg*8
    const int lrow = tid >> 3, lq = tid & 7;      // x loader
    const int wn = tid >> 3, wq = tid & 7;        // W loader
    const float* xb = x + (size_t)m0 * D_MODEL;
    float4 px[8], pw;
#pragma unroll
    for (int i = 0; i < 8; i++)
        px[i] = *(const float4*)(xb + (size_t)(lrow + 32 * i) * D_MODEL + lq * 4);
    pw = *(const float4*)(Win + (size_t)wn * D_MODEL + wq * 4);

    u64 acc[2][8];
#pragma unroll
    for (int p = 0; p < 2; p++)
#pragma unroll
        for (int mo = 0; mo < 8; mo++) acc[p][mo] = 0ull;

    for (int c = 0; c < 32; c++) {
        __syncthreads();
#pragma unroll
        for (int i = 0; i < 8; i++) {
            int row = lrow + 32 * i;
            xs[(lq * 4 + 0) * 260 + row] = px[i].x;
            xs[(lq * 4 + 1) * 260 + row] = px[i].y;
            xs[(lq * 4 + 2) * 260 + row] = px[i].z;
            xs[(lq * 4 + 3) * 260 + row] = px[i].w;
        }
        ws[(wq * 4 + 0) * 36 + wn] = pw.x;
        ws[(wq * 4 + 1) * 36 + wn] = pw.y;
        ws[(wq * 4 + 2) * 36 + wn] = pw.z;
        ws[(wq * 4 + 3) * 36 + wn] = pw.w;
        __syncthreads();
        if (c < 31) {
            const int dc = (c + 1) * 32;
#pragma unroll
            for (int i = 0; i < 8; i++)
                px[i] = *(const float4*)(xb + (size_t)(lrow + 32 * i) * D_MODEL + dc + lq * 4);
            pw = *(const float4*)(Win + (size_t)wn * D_MODEL + dc + wq * 4);
        }
#pragma unroll
        for (int kk = 0; kk < 32; kk++) {
            ulonglong2 xv = *(const ulonglong2*)(xs + kk * 260 + rg * 4);
            float w[8];
            *(float4*)&w[0] = *(const float4*)(ws + kk * 36 + mg * 8);
            *(float4*)&w[4] = *(const float4*)(ws + kk * 36 + mg * 8 + 4);
#pragma unroll
            for (int mo = 0; mo < 8; mo++) {
                u64 wp = pack2(w[mo], w[mo]);
                acc[0][mo] = fma2(xv.x, wp, acc[0][mo]);
                acc[1][mo] = fma2(xv.y, wp, acc[1][mo]);
            }
        }
    }
#pragma unroll
    for (int r = 0; r < 4; r++) {
        const int p = r >> 1, h = r & 1;
        float v[8];
#pragma unroll
        for (int mo = 0; mo < 8; mo++) {
            float2 f = unpack2(acc[p][mo]);
            v[mo] = h ? f.y : f.x;
        }
        float* dst = g_xp + (size_t)(m0 + rg * 4 + r) * HALF + mg * 8;
        *(float4*)dst       = make_float4(v[0], v[1], v[2], v[3]);
        *(float4*)(dst + 4) = make_float4(v[4], v[5], v[6], v[7]);
    }
}

// FIR: 32-tap causal conv per (batch, mode-pair); taps + window in registers.
__global__ __launch_bounds__(128)
void k_fir() {
    const int tid = threadIdx.x, np = tid & 15, slot = tid >> 4;
    const int m0 = blockIdx.x * 256 + slot * 32;
    const int t0 = m0 & (T_SEQ - 1);
    const u64* xp2 = (const u64*)g_xp;
    u64* y2 = (u64*)g_y;
    u64 K[TAPS], w[TAPS];
#pragma unroll
    for (int s = 0; s < TAPS; s++) K[s] = g_Kp[s * 16 + np];
#pragma unroll
    for (int s = 1; s < TAPS; s++) {
        u64 v = 0ull;
        if (t0 >= s) v = xp2[(size_t)(m0 - s) * 16 + np];
        w[(TAPS - s) & (TAPS - 1)] = v;
    }
#pragma unroll
    for (int tt = 0; tt < 32; tt++) {
        w[tt & (TAPS - 1)] = xp2[(size_t)(m0 + tt) * 16 + np];
        u64 acc = 0ull;
#pragma unroll
        for (int s = 0; s < TAPS; s++)
            acc = fma2(K[s], w[(tt - s) & (TAPS - 1)], acc);
        y2[(size_t)(m0 + tt) * 16 + np] = acc;
    }
}

// GEMM2: out[m,d] = sum_n y[m,n]*Wout[d,n]. Tile 128 rows x 64 cols.
__global__ __launch_bounds__(256)
void k_out(const float* __restrict__ Wo, float* __restrict__ out) {
    __shared__ float ysT[32 * 132];  // [n][row]
    __shared__ float wsT[32 * 68];   // [n][col]
    const int tid = threadIdx.x;
    const int m0 = blockIdx.x * 128, c0 = blockIdx.y * 64;

    {   // y tile: 128 rows x 32 modes. One pass: row = tid>>1 (0..127), q = tid&1.
        const int row = tid >> 1, q = tid & 1;
        const float* src = g_y + (size_t)(m0 + row) * HALF + q * 16;
        float4 v0 = *(const float4*)(src + 0);
        float4 v1 = *(const float4*)(src + 4);
        float4 v2 = *(const float4*)(src + 8);
        float4 v3 = *(const float4*)(src + 12);
        const float vv[16] = {v0.x,v0.y,v0.z,v0.w, v1.x,v1.y,v1.z,v1.w,
                              v2.x,v2.y,v2.z,v2.w, v3.x,v3.y,v3.z,v3.w};
#pragma unroll
        for (int j = 0; j < 16; j++) ysT[(q * 16 + j) * 132 + row] = vv[j];
    }
#pragma unroll
    for (int i = 0; i < 2; i++) {   // Wout tile: 64 cols x 32 k. 512 float4s.
        const int f = tid + 256 * i;
        const int dd = f >> 3, q = f & 7;     // col 0..63, k-quad 0..7
        float4 v = *(const float4*)(Wo + (size_t)(c0 + dd) * HALF + q * 4);
        wsT[(q * 4 + 0) * 68 + dd] = v.x;
        wsT[(q * 4 + 1) * 68 + dd] = v.y;
        wsT[(q * 4 + 2) * 68 + dd] = v.z;
        wsT[(q * 4 + 3) * 68 + dd] = v.w;
    }
    __syncthreads();

    const int rg = tid >> 3, cg = tid & 7;  // rows rg*4, cols cg*8
    u64 acc[4][4];
#pragma unroll
    for (int r = 0; r < 4; r++)
#pragma unroll
        for (int cp = 0; cp < 4; cp++) acc[r][cp] = 0ull;
#pragma unroll
    for (int n = 0; n < 32; n++) {
        float4 yv = *(const float4*)(ysT + n * 132 + rg * 4);
        ulonglong2 wv0 = *(const ulonglong2*)(wsT + n * 68 + cg * 8);
        ulonglong2 wv1 = *(const ulonglong2*)(wsT + n * 68 + cg * 8 + 4);
        u64 wq[4] = {wv0.x, wv0.y, wv1.x, wv1.y};
        float yr[4] = {yv.x, yv.y, yv.z, yv.w};
#pragma unroll
        for (int r = 0; r < 4; r++) {
            u64 yp = pack2(yr[r], yr[r]);
#pragma unroll
            for (int cp = 0; cp < 4; cp++)
                acc[r][cp] = fma2(yp, wq[cp], acc[r][cp]);
        }
    }
#pragma unroll
    for (int r = 0; r < 4; r++) {
        float* dst = out + (size_t)(m0 + rg * 4 + r) * D_MODEL + c0 + cg * 8;
        *(ulonglong2*)dst       = make_ulonglong2(acc[r][0], acc[r][1]);
        *(ulonglong2*)(dst + 4) = make_ulonglong2(acc[r][2], acc[r][3]);
    }
}

extern "C" void kernel_launch(void* const* d_in, const int* in_sizes, int n_in,
                              void* d_out, int out_size) {
    const float* x       = (const float*)d_in[0];
    const float* log_tau = (const float*)d_in[1];
    const float* freq    = (const float*)d_in[2];
    const float* Bp      = (const float*)d_in[3];
    const float* Cp      = (const float*)d_in[4];
    const float* log_dt  = (const float*)d_in[5];
    const float* W_in    = (const float*)d_in[6];
    const float* W_out   = (const float*)d_in[7];
    float* out = (float*)d_out;

    k_prep<<<1, 512>>>(log_tau, freq, Bp, Cp, log_dt);
    k_proj<<<M_TOTAL / 256, 256>>>(x, W_in);
    k_fir<<<M_TOTAL / 256, 128>>>();
    k_out<<<dim3(M_TOTAL / 128, D_MODEL / 64), 256>>>(W_out, out);
}

// round 8
// speedup vs baseline: 1.0870x; 1.0870x over previous
#include <cuda_runtime.h>
#include <cuda_bf16.h>
#include <math.h>

typedef unsigned long long u64;
#define M_TOTAL 32768
#define D_MODEL 1024
#define HALF 32
#define T_SEQ 8192
#define TAPS 32

__device__ float g_xp[M_TOTAL * HALF];
__device__ float g_y[M_TOTAL * HALF];
__device__ u64   g_Kp[TAPS * 16];

__device__ __forceinline__ u64 fma2(u64 a, u64 b, u64 c) {
    u64 d; asm("fma.rn.f32x2 %0, %1, %2, %3;" : "=l"(d) : "l"(a), "l"(b), "l"(c)); return d;
}
__device__ __forceinline__ u64 pack2(float lo, float hi) {
    u64 r; asm("mov.b64 %0, {%1, %2};" : "=l"(r) : "f"(lo), "f"(hi)); return r;
}
__device__ __forceinline__ float2 unpack2(u64 v) {
    float2 f; asm("mov.b64 {%0, %1}, %2;" : "=f"(f.x), "=f"(f.y) : "l"(v)); return f;
}

// FIR taps (unchanged, proven): K[n,s] = exp(gain_n - tau*dt*s) * cos(s*angle_n).
__global__ void k_prep(const float* __restrict__ log_tau, const float* __restrict__ freq,
                       const float* __restrict__ Bp, const float* __restrict__ Cp,
                       const float* __restrict__ log_dt) {
    int tid = threadIdx.x, s = tid >> 4, np = tid & 15;
    double dt = exp((double)log_dt[0]);
    float k[2];
#pragma unroll
    for (int j = 0; j < 2; j++) {
        int n = np * 2 + j;
        double tau   = fmax(exp((double)log_tau[n]), 1e-4);
        double angle = (double)freq[n] * dt;
        double gain  = log(fabs((double)Bp[n]) + 1e-9) + log(fabs((double)Cp[n]) + 1e-9);
        k[j] = (float)(exp(gain - tau * dt * (double)s) * cos((double)s * angle));
    }
    g_Kp[s * 16 + np] = pack2(k[0], k[1]);
}

// GEMM1: xp[m,n] = sum_d x[m,d]*Win[n,d].
// Tile 128 rows x 32 modes, grid 256, 256 threads.
// Thread: 2 rows (one f32x2 lane-pair) x 8 modes. Modes warp-uniform -> ws broadcast.
__global__ __launch_bounds__(256, 1)
void k_proj(const float* __restrict__ x, const float* __restrict__ Win) {
    __shared__ float xs[32][130];   // [k][row] (pad 130)
    __shared__ float ws[32][36];    // [k][mode] (pad 36)
    const int tid = threadIdx.x, m0 = blockIdx.x * 128;
    const int mg = tid >> 6;        // 0..3 -> modes mg*8..+7 (uniform per 2 warps)
    const int rg = tid & 63;        // rows 2rg, 2rg+1
    const int lrow = tid >> 3, lq = tid & 7;   // x loader: rows lrow+32i, k-quad lq
    const int wn = tid >> 3, wq = tid & 7;     // W loader: mode wn, k-quad wq
    const float* xb = x + (size_t)m0 * D_MODEL;

    float4 px[4], pw;
#pragma unroll
    for (int i = 0; i < 4; i++)
        px[i] = *(const float4*)(xb + (size_t)(lrow + 32 * i) * D_MODEL + lq * 4);
    pw = *(const float4*)(Win + (size_t)wn * D_MODEL + wq * 4);

    u64 acc[8];
#pragma unroll
    for (int mo = 0; mo < 8; mo++) acc[mo] = 0ull;

#pragma unroll 1
    for (int c = 0; c < 32; c++) {
        __syncthreads();
#pragma unroll
        for (int i = 0; i < 4; i++) {
            int row = lrow + 32 * i;
            xs[lq * 4 + 0][row] = px[i].x;
            xs[lq * 4 + 1][row] = px[i].y;
            xs[lq * 4 + 2][row] = px[i].z;
            xs[lq * 4 + 3][row] = px[i].w;
        }
        ws[wq * 4 + 0][wn] = pw.x;
        ws[wq * 4 + 1][wn] = pw.y;
        ws[wq * 4 + 2][wn] = pw.z;
        ws[wq * 4 + 3][wn] = pw.w;
        __syncthreads();
        if (c < 31) {
            const int dc = (c + 1) * 32;
#pragma unroll
            for (int i = 0; i < 4; i++)
                px[i] = *(const float4*)(xb + (size_t)(lrow + 32 * i) * D_MODEL + dc + lq * 4);
            pw = *(const float4*)(Win + (size_t)wn * D_MODEL + dc + wq * 4);
        }
#pragma unroll
        for (int kk = 0; kk < 32; kk++) {
            u64 xv = *(const u64*)&xs[kk][rg * 2];          // 2 rows, per-lane
            float w[8];                                      // 8 modes, broadcast
            *(float4*)&w[0] = *(const float4*)&ws[kk][mg * 8];
            *(float4*)&w[4] = *(const float4*)&ws[kk][mg * 8 + 4];
#pragma unroll
            for (int mo = 0; mo < 8; mo++)
                acc[mo] = fma2(xv, pack2(w[mo], w[mo]), acc[mo]);
        }
    }
    float r0v[8], r1v[8];
#pragma unroll
    for (int mo = 0; mo < 8; mo++) {
        float2 f = unpack2(acc[mo]);
        r0v[mo] = f.x; r1v[mo] = f.y;
    }
    float* d0 = g_xp + (size_t)(m0 + rg * 2) * HALF + mg * 8;
    *(float4*)d0       = make_float4(r0v[0], r0v[1], r0v[2], r0v[3]);
    *(float4*)(d0 + 4) = make_float4(r0v[4], r0v[5], r0v[6], r0v[7]);
    float* d1 = d0 + HALF;
    *(float4*)d1       = make_float4(r1v[0], r1v[1], r1v[2], r1v[3]);
    *(float4*)(d1 + 4) = make_float4(r1v[4], r1v[5], r1v[6], r1v[7]);
}

// FIR (unchanged, proven): 32-tap causal conv per (batch, mode-pair).
__global__ __launch_bounds__(128)
void k_fir() {
    const int tid = threadIdx.x, np = tid & 15, slot = tid >> 4;
    const int m0 = blockIdx.x * 256 + slot * 32;
    const int t0 = m0 & (T_SEQ - 1);
    const u64* xp2 = (const u64*)g_xp;
    u64* y2 = (u64*)g_y;
    u64 K[TAPS], w[TAPS];
#pragma unroll
    for (int s = 0; s < TAPS; s++) K[s] = g_Kp[s * 16 + np];
#pragma unroll
    for (int s = 1; s < TAPS; s++) {
        u64 v = 0ull;
        if (t0 >= s) v = xp2[(size_t)(m0 - s) * 16 + np];
        w[(TAPS - s) & (TAPS - 1)] = v;
    }
#pragma unroll
    for (int tt = 0; tt < 32; tt++) {
        w[tt & (TAPS - 1)] = xp2[(size_t)(m0 + tt) * 16 + np];
        u64 acc = 0ull;
#pragma unroll
        for (int s = 0; s < TAPS; s++)
            acc = fma2(K[s], w[(tt - s) & (TAPS - 1)], acc);
        y2[(size_t)(m0 + tt) * 16 + np] = acc;
    }
}

// GEMM2: out[m,d] = sum_n y[m,n]*Wout[d,n].
// Tile 32 rows x 256 cols, 128 threads. Warp = 8 rows x 256 cols;
// thread = 8 rows x 8 cols. y rows warp-uniform -> broadcast.
__global__ __launch_bounds__(128)
void k_out(const float* __restrict__ Wo, float* __restrict__ out) {
    __shared__ float ys[32][36];    // [row][n]
    __shared__ float ws[32][260];   // [n][col] (pad 260)
    const int tid = threadIdx.x;
    const int m0 = blockIdx.x * 32, c0 = blockIdx.y * 256;
    const int wid = tid >> 5, lane = tid & 31;

#pragma unroll
    for (int i = 0; i < 2; i++) {   // y tile: 32 rows x 32 n (natural layout, STS.128)
        const int f = tid + 128 * i;
        const int row = f >> 3, q = f & 7;
        *(float4*)&ys[row][q * 4] =
            *(const float4*)(g_y + (size_t)(m0 + row) * HALF + q * 4);
    }
#pragma unroll
    for (int i = 0; i < 16; i++) {  // Wo tile: 256 cols x 32 n, transposed
        const int f = tid + 128 * i;
        const int d = f >> 3, q = f & 7;
        float4 v = *(const float4*)(Wo + (size_t)(c0 + d) * HALF + q * 4);
        ws[q * 4 + 0][d] = v.x;
        ws[q * 4 + 1][d] = v.y;
        ws[q * 4 + 2][d] = v.z;
        ws[q * 4 + 3][d] = v.w;
    }
    __syncthreads();

    const int r0 = wid * 8;         // 8 rows per warp (uniform across lanes)
    const int cc = lane * 8;        // 8 cols per lane
    u64 acc[8][4];
#pragma unroll
    for (int r = 0; r < 8; r++)
#pragma unroll
        for (int cp = 0; cp < 4; cp++) acc[r][cp] = 0ull;

#pragma unroll
    for (int nq = 0; nq < 8; nq++) {
        float4 yv[8];
#pragma unroll
        for (int r = 0; r < 8; r++)             // broadcast reads
            yv[r] = *(const float4*)&ys[r0 + r][nq * 4];
#pragma unroll
        for (int j = 0; j < 4; j++) {
            const int n = nq * 4 + j;
            ulonglong2 w0 = *(const ulonglong2*)&ws[n][cc];
            ulonglong2 w1 = *(const ulonglong2*)&ws[n][cc + 4];
            u64 wv[4] = {w0.x, w0.y, w1.x, w1.y};
#pragma unroll
            for (int r = 0; r < 8; r++) {
                const float yr = (&yv[r].x)[j];
                u64 yp = pack2(yr, yr);
#pragma unroll
                for (int cp = 0; cp < 4; cp++)
                    acc[r][cp] = fma2(yp, wv[cp], acc[r][cp]);
            }
        }
    }
#pragma unroll
    for (int r = 0; r < 8; r++) {
        float* dst = out + (size_t)(m0 + r0 + r) * D_MODEL + c0 + cc;
        *(ulonglong2*)dst       = make_ulonglong2(acc[r][0], acc[r][1]);
        *(ulonglong2*)(dst + 4) = make_ulonglong2(acc[r][2], acc[r][3]);
    }
}

extern "C" void kernel_launch(void* const* d_in, const int* in_sizes, int n_in,
                              void* d_out, int out_size) {
    const float* x       = (const float*)d_in[0];
    const float* log_tau = (const float*)d_in[1];
    const float* freq    = (const float*)d_in[2];
    const float* Bp      = (const float*)d_in[3];
    const float* Cp      = (const float*)d_in[4];
    const float* log_dt  = (const float*)d_in[5];
    const float* W_in    = (const float*)d_in[6];
    const float* W_out   = (const float*)d_in[7];
    float* out = (float*)d_out;

    k_prep<<<1, 512>>>(log_tau, freq, Bp, Cp, log_dt);
    k_proj<<<M_TOTAL / 128, 256>>>(x, W_in);
    k_fir<<<M_TOTAL / 256, 128>>>();
    k_out<<<dim3(M_TOTAL / 32, D_MODEL / 256), 128>>>(W_out, out);
}